// round 1
// baseline (speedup 1.0000x reference)
#include <cuda_runtime.h>

// Problem geometry (fixed by the dataset)
#define WW 256
#define HH 256
#define DD 64
#define HWW (HH*WW)        // 65536
#define CS  (DD*HWW)       // 4194304 elements per (channel, batch-slice)

// Global accumulators (graph-capturable scratch; no allocations)
__device__ double g_sum;
__device__ double g_cnt;

__global__ void init_kernel() {
    g_sum = 0.0;
    g_cnt = 0.0;
}

__global__ void final_kernel(float* out) {
    out[0] = (float)(g_sum / g_cnt);
}

__device__ __forceinline__ float4 ldf4(const float* p) {
    return *reinterpret_cast<const float4*>(p);
}

// e = predicts - targets for one channel, vectorized
__device__ __forceinline__ float4 e4(const float* __restrict__ p,
                                     const float* __restrict__ t, int off) {
    float4 a = ldf4(p + off);
    float4 b = ldf4(t + off);
    return make_float4(a.x - b.x, a.y - b.y, a.z - b.z, a.w - b.w);
}

#define GET(v4, i) ((i)==0?(v4).x:((i)==1?(v4).y:((i)==2?(v4).z:(v4).w)))

struct MaskCtx {
    const float* Mb;
    int baseHm, baseC, baseHp;
    int bL, bR;
    bool needL, needR;
};

// 4 bits: bit i set iff all 9 mask values (3 h-rows x 3 w-cols) in plane pd
// around output w0+i are 1.
__device__ __forceinline__ unsigned planeMask(const MaskCtx& c, int pd) {
    int o = pd * HWW;
    float4 r0 = ldf4(c.Mb + o + c.baseHm);
    float4 r1 = ldf4(c.Mb + o + c.baseC);
    float4 r2 = ldf4(c.Mb + o + c.baseHp);
    float4 cm;
    cm.x = fminf(r0.x, fminf(r1.x, r2.x));
    cm.y = fminf(r0.y, fminf(r1.y, r2.y));
    cm.z = fminf(r0.z, fminf(r1.z, r2.z));
    cm.w = fminf(r0.w, fminf(r1.w, r2.w));
    float L = __shfl_up_sync(0xffffffffu, cm.w, 1);
    float R = __shfl_down_sync(0xffffffffu, cm.x, 1);
    if (c.needL) {
        float a = c.Mb[o + c.bL - WW];
        float b = c.Mb[o + c.bL];
        float d = c.Mb[o + c.bL + WW];
        L = fminf(a, fminf(b, d));
    }
    if (c.needR) {
        float a = c.Mb[o + c.bR - WW];
        float b = c.Mb[o + c.bR];
        float d = c.Mb[o + c.bR + WW];
        R = fminf(a, fminf(b, d));
    }
    unsigned m = 0;
    if (fminf(L,    fminf(cm.x, cm.y)) > 0.5f) m |= 1u;
    if (fminf(cm.x, fminf(cm.y, cm.z)) > 0.5f) m |= 2u;
    if (fminf(cm.y, fminf(cm.z, cm.w)) > 0.5f) m |= 4u;
    if (fminf(cm.z, fminf(cm.w, R))    > 0.5f) m |= 8u;
    return m;
}

// One thread owns a 4-wide (float4) strip at fixed (b, h), sliding along d.
// Warp = 32 consecutive float4 chunks = half a W-row; 2 warps per (b,h) row.
__global__ __launch_bounds__(128)
void vort_kernel(const float* __restrict__ P,
                 const float* __restrict__ T,
                 const float* __restrict__ M) {
    const int tid  = threadIdx.x;
    const int lane = tid & 31;
    const int wib  = tid >> 5;                    // warp in block: 0..3
    const int gw   = blockIdx.x * 4 + wib;        // 0..1015
    const int row  = gw >> 1;                     // 0..507
    const int half = gw & 1;                      // which half of the W row
    const int b    = row / 254;
    const int h    = row % 254 + 1;               // 1..254
    const int w0   = (half * 32 + lane) * 4;      // 0..252

    const int d0 = 1 + blockIdx.y * 31;           // dseg 0 -> d=1..31, 1 -> 32..62

    const float* P1 = P + (size_t)b * 4 * CS + CS;
    const float* P2 = P1 + CS;
    const float* P3 = P2 + CS;
    const float* T1 = T + (size_t)b * 4 * CS + CS;
    const float* T2 = T1 + CS;
    const float* T3 = T2 + CS;
    const float* Mb = M + (size_t)b * CS;

    const int baseC  = h * WW + w0;
    const int baseHm = baseC - WW;
    const int baseHp = baseC + WW;

    const bool needR = (half == 0 && lane == 31);   // needs value at w=128
    const bool needL = (half == 1 && lane == 0);    // needs value at w=127
    const int  bR = h * WW + 128;
    const int  bL = h * WW + 127;

    MaskCtx mc;
    mc.Mb = Mb; mc.baseHm = baseHm; mc.baseC = baseC; mc.baseHp = baseHp;
    mc.bL = bL; mc.bR = bR; mc.needL = needL; mc.needR = needR;

    unsigned validBits = 0xFu;
    if (half == 0 && lane == 0)  validBits &= ~1u;   // w=0 excluded
    if (half == 1 && lane == 31) validBits &= ~8u;   // w=255 excluded

    // Warm-up: planes d0-1 and d0 for u (ch1), v (ch2) and mask AND-bits
    float4 u_km1 = e4(P1, T1, (d0 - 1) * HWW + baseC);
    float4 u_k   = e4(P1, T1,  d0      * HWW + baseC);
    float4 v_km1 = e4(P2, T2, (d0 - 1) * HWW + baseC);
    float4 v_k   = e4(P2, T2,  d0      * HWW + baseC);
    unsigned m_km1 = planeMask(mc, d0 - 1);
    unsigned m_k   = planeMask(mc, d0);

    float acc = 0.0f;
    int   cnt = 0;

    #pragma unroll 1
    for (int d = d0; d < d0 + 31; ++d) {
        const int oN = (d + 1) * HWW;
        const int oC = d * HWW;

        float4 u_kp1 = e4(P1, T1, oN + baseC);
        float4 v_kp1 = e4(P2, T2, oN + baseC);
        float4 uhm   = e4(P1, T1, oC + baseHm);
        float4 uhp   = e4(P1, T1, oC + baseHp);
        float4 w3hm  = e4(P3, T3, oC + baseHm);
        float4 w3hp  = e4(P3, T3, oC + baseHp);
        float4 w3c   = e4(P3, T3, oC + baseC);
        unsigned m_kp1 = planeMask(mc, d + 1);

        // Cross-warp boundary values (plane d, row h) for the w+-1 stencils
        float vLs = 0.f, vRs = 0.f, w3Ls = 0.f, w3Rs = 0.f;
        if (needL) {
            int ix = oC + bL;
            vLs  = P2[ix] - T2[ix];
            w3Ls = P3[ix] - T3[ix];
        }
        if (needR) {
            int ix = oC + bR;
            vRs  = P2[ix] - T2[ix];
            w3Rs = P3[ix] - T3[ix];
        }

        float v_l  = __shfl_up_sync(0xffffffffu, v_k.w, 1);
        float v_r  = __shfl_down_sync(0xffffffffu, v_k.x, 1);
        float w3_l = __shfl_up_sync(0xffffffffu, w3c.w, 1);
        float w3_r = __shfl_down_sync(0xffffffffu, w3c.x, 1);
        if (needL) { v_l = vLs; w3_l = w3Ls; }
        if (needR) { v_r = vRs; w3_r = w3Rs; }

        unsigned mm = m_km1 & m_k & m_kp1 & validBits;

        #pragma unroll
        for (int i = 0; i < 4; ++i) {
            float w3l = (i == 0) ? w3_l : GET(w3c, i - 1);
            float w3r = (i == 3) ? w3_r : GET(w3c, i + 1);
            float vl  = (i == 0) ? v_l  : GET(v_k, i - 1);
            float vr  = (i == 3) ? v_r  : GET(v_k, i + 1);
            float Ox = (GET(w3hp, i) - GET(w3hm, i)) - (GET(v_kp1, i) - GET(v_km1, i));
            float Oy = (GET(u_kp1, i) - GET(u_km1, i)) - (w3r - w3l);
            float Oz = (vr - vl) - (GET(uhp, i) - GET(uhm, i));
            if ((mm >> i) & 1u) {
                acc += sqrtf(fmaf(Ox, Ox, fmaf(Oy, Oy, Oz * Oz)));
                cnt++;
            }
        }

        // slide along d
        u_km1 = u_k;  u_k = u_kp1;
        v_km1 = v_k;  v_k = v_kp1;
        m_km1 = m_k;  m_k = m_kp1;
    }

    // Reduction: warp shfl -> smem -> one double atomic per block
    #pragma unroll
    for (int o = 16; o; o >>= 1) {
        acc += __shfl_down_sync(0xffffffffu, acc, o);
        cnt += __shfl_down_sync(0xffffffffu, cnt, o);
    }
    __shared__ float sacc[4];
    __shared__ int   scnt[4];
    if (lane == 0) { sacc[wib] = acc; scnt[wib] = cnt; }
    __syncthreads();
    if (tid == 0) {
        float a = sacc[0] + sacc[1] + sacc[2] + sacc[3];
        int   c = scnt[0] + scnt[1] + scnt[2] + scnt[3];
        atomicAdd(&g_sum, (double)a);
        atomicAdd(&g_cnt, (double)c);
    }
}

extern "C" void kernel_launch(void* const* d_in, const int* in_sizes, int n_in,
                              void* d_out, int out_size) {
    const float* P = (const float*)d_in[0];   // predicts (2,4,64,256,256)
    const float* T = (const float*)d_in[1];   // targets  (2,4,64,256,256)
    const float* M = (const float*)d_in[2];   // masks    (2,1,64,256,256)
    float* out = (float*)d_out;

    init_kernel<<<1, 1>>>();
    dim3 grid(254, 2);           // 254 blocks x 4 warps = 1016 warps per d-segment
    vort_kernel<<<grid, 128>>>(P, T, M);
    final_kernel<<<1, 1>>>(out);
}

// round 6
// speedup vs baseline: 1.0574x; 1.0574x over previous
#include <cuda_runtime.h>

// Problem geometry (fixed by the dataset)
#define WW 256
#define HH 256
#define DD 64
#define HWW (HH*WW)        // 65536
#define CS  (DD*HWW)       // 4194304 elements per (channel, batch-slice)

#define NSEG 8             // d-segments (62 interior planes / 8)
#define PS   8             // planes per segment (last segment: 6)

// Global accumulators. Static zero-init; final_kernel resets after reading,
// so every graph replay starts from zero (deterministic).
__device__ double g_sum;
__device__ double g_cnt;

__global__ void final_kernel(float* out) {
    out[0] = (float)(g_sum / g_cnt);
    g_sum = 0.0;
    g_cnt = 0.0;
}

__device__ __forceinline__ float4 ldf4(const float* p) {
    return *reinterpret_cast<const float4*>(p);
}

// e = predicts - targets for one channel, vectorized
__device__ __forceinline__ float4 e4(const float* __restrict__ p,
                                     const float* __restrict__ t, int off) {
    float4 a = ldf4(p + off);
    float4 b = ldf4(t + off);
    return make_float4(a.x - b.x, a.y - b.y, a.z - b.z, a.w - b.w);
}

#define GET(v4, i) ((i)==0?(v4).x:((i)==1?(v4).y:((i)==2?(v4).z:(v4).w)))

struct MaskCtx {
    const float* Mb;
    int baseHm, baseC, baseHp;
    int bL, bR;
    bool needL, needR;
};

// 4 bits: bit i set iff all 9 mask values (3 h-rows x 3 w-cols) in plane pd
// around output w0+i are 1.
__device__ __forceinline__ unsigned planeMask(const MaskCtx& c, int pd) {
    int o = pd * HWW;
    float4 r0 = ldf4(c.Mb + o + c.baseHm);
    float4 r1 = ldf4(c.Mb + o + c.baseC);
    float4 r2 = ldf4(c.Mb + o + c.baseHp);
    float4 cm;
    cm.x = fminf(r0.x, fminf(r1.x, r2.x));
    cm.y = fminf(r0.y, fminf(r1.y, r2.y));
    cm.z = fminf(r0.z, fminf(r1.z, r2.z));
    cm.w = fminf(r0.w, fminf(r1.w, r2.w));
    float L = __shfl_up_sync(0xffffffffu, cm.w, 1);
    float R = __shfl_down_sync(0xffffffffu, cm.x, 1);
    if (c.needL) {
        float a = c.Mb[o + c.bL - WW];
        float b = c.Mb[o + c.bL];
        float d = c.Mb[o + c.bL + WW];
        L = fminf(a, fminf(b, d));
    }
    if (c.needR) {
        float a = c.Mb[o + c.bR - WW];
        float b = c.Mb[o + c.bR];
        float d = c.Mb[o + c.bR + WW];
        R = fminf(a, fminf(b, d));
    }
    unsigned m = 0;
    if (fminf(L,    fminf(cm.x, cm.y)) > 0.5f) m |= 1u;
    if (fminf(cm.x, fminf(cm.y, cm.z)) > 0.5f) m |= 2u;
    if (fminf(cm.y, fminf(cm.z, cm.w)) > 0.5f) m |= 4u;
    if (fminf(cm.z, fminf(cm.w, R))    > 0.5f) m |= 8u;
    return m;
}

// One thread owns a 4-wide (float4) strip at fixed (b, h), sliding along a
// short d-segment. Warp = 32 consecutive float4 chunks = half a W-row.
__global__ __launch_bounds__(128)
void vort_kernel(const float* __restrict__ P,
                 const float* __restrict__ T,
                 const float* __restrict__ M) {
    const int tid  = threadIdx.x;
    const int lane = tid & 31;
    const int wib  = tid >> 5;                    // warp in block: 0..3
    const int gw   = blockIdx.x * 4 + wib;        // 0..1015
    const int row  = gw >> 1;                     // 0..507
    const int half = gw & 1;                      // which half of the W row
    const int b    = row / 254;
    const int h    = row % 254 + 1;               // 1..254
    const int w0   = (half * 32 + lane) * 4;      // 0..252

    const int d0 = 1 + blockIdx.y * PS;
    const int dN = min(d0 + PS, DD - 1);          // exclusive end (<= 63)

    const float* P1 = P + (size_t)b * 4 * CS + CS;
    const float* P2 = P1 + CS;
    const float* P3 = P2 + CS;
    const float* T1 = T + (size_t)b * 4 * CS + CS;
    const float* T2 = T1 + CS;
    const float* T3 = T2 + CS;
    const float* Mb = M + (size_t)b * CS;

    const int baseC  = h * WW + w0;
    const int baseHm = baseC - WW;
    const int baseHp = baseC + WW;

    const bool needR = (half == 0 && lane == 31);   // needs value at w=128
    const bool needL = (half == 1 && lane == 0);    // needs value at w=127
    const int  bR = h * WW + 128;
    const int  bL = h * WW + 127;

    MaskCtx mc;
    mc.Mb = Mb; mc.baseHm = baseHm; mc.baseC = baseC; mc.baseHp = baseHp;
    mc.bL = bL; mc.bR = bR; mc.needL = needL; mc.needR = needR;

    unsigned validBits = 0xFu;
    if (half == 0 && lane == 0)  validBits &= ~1u;   // w=0 excluded
    if (half == 1 && lane == 31) validBits &= ~8u;   // w=255 excluded

    // Warm-up: planes d0-1 and d0 for u (ch1), v (ch2) and mask AND-bits
    float4 u_km1 = e4(P1, T1, (d0 - 1) * HWW + baseC);
    float4 u_k   = e4(P1, T1,  d0      * HWW + baseC);
    float4 v_km1 = e4(P2, T2, (d0 - 1) * HWW + baseC);
    float4 v_k   = e4(P2, T2,  d0      * HWW + baseC);
    unsigned m_km1 = planeMask(mc, d0 - 1);
    unsigned m_k   = planeMask(mc, d0);

    float acc = 0.0f;
    int   cnt = 0;

    #pragma unroll 1
    for (int d = d0; d < dN; ++d) {
        const int oN = (d + 1) * HWW;
        const int oC = d * HWW;

        float4 u_kp1 = e4(P1, T1, oN + baseC);
        float4 v_kp1 = e4(P2, T2, oN + baseC);
        float4 uhm   = e4(P1, T1, oC + baseHm);
        float4 uhp   = e4(P1, T1, oC + baseHp);
        float4 w3hm  = e4(P3, T3, oC + baseHm);
        float4 w3hp  = e4(P3, T3, oC + baseHp);
        float4 w3c   = e4(P3, T3, oC + baseC);
        unsigned m_kp1 = planeMask(mc, d + 1);

        // Cross-warp boundary values (plane d, row h) for the w+-1 stencils
        float vLs = 0.f, vRs = 0.f, w3Ls = 0.f, w3Rs = 0.f;
        if (needL) {
            int ix = oC + bL;
            vLs  = P2[ix] - T2[ix];
            w3Ls = P3[ix] - T3[ix];
        }
        if (needR) {
            int ix = oC + bR;
            vRs  = P2[ix] - T2[ix];
            w3Rs = P3[ix] - T3[ix];
        }

        float v_l  = __shfl_up_sync(0xffffffffu, v_k.w, 1);
        float v_r  = __shfl_down_sync(0xffffffffu, v_k.x, 1);
        float w3_l = __shfl_up_sync(0xffffffffu, w3c.w, 1);
        float w3_r = __shfl_down_sync(0xffffffffu, w3c.x, 1);
        if (needL) { v_l = vLs; w3_l = w3Ls; }
        if (needR) { v_r = vRs; w3_r = w3Rs; }

        unsigned mm = m_km1 & m_k & m_kp1 & validBits;

        #pragma unroll
        for (int i = 0; i < 4; ++i) {
            float w3l = (i == 0) ? w3_l : GET(w3c, i - 1);
            float w3r = (i == 3) ? w3_r : GET(w3c, i + 1);
            float vl  = (i == 0) ? v_l  : GET(v_k, i - 1);
            float vr  = (i == 3) ? v_r  : GET(v_k, i + 1);
            float Ox = (GET(w3hp, i) - GET(w3hm, i)) - (GET(v_kp1, i) - GET(v_km1, i));
            float Oy = (GET(u_kp1, i) - GET(u_km1, i)) - (w3r - w3l);
            float Oz = (vr - vl) - (GET(uhp, i) - GET(uhm, i));
            if ((mm >> i) & 1u) {
                acc += sqrtf(fmaf(Ox, Ox, fmaf(Oy, Oy, Oz * Oz)));
                cnt++;
            }
        }

        // slide along d
        u_km1 = u_k;  u_k = u_kp1;
        v_km1 = v_k;  v_k = v_kp1;
        m_km1 = m_k;  m_k = m_kp1;
    }

    // Reduction: warp shfl -> smem -> one double atomic per block
    #pragma unroll
    for (int o = 16; o; o >>= 1) {
        acc += __shfl_down_sync(0xffffffffu, acc, o);
        cnt += __shfl_down_sync(0xffffffffu, cnt, o);
    }
    __shared__ float sacc[4];
    __shared__ int   scnt[4];
    if (lane == 0) { sacc[wib] = acc; scnt[wib] = cnt; }
    __syncthreads();
    if (tid == 0) {
        float a = sacc[0] + sacc[1] + sacc[2] + sacc[3];
        int   c = scnt[0] + scnt[1] + scnt[2] + scnt[3];
        atomicAdd(&g_sum, (double)a);
        atomicAdd(&g_cnt, (double)c);
    }
}

extern "C" void kernel_launch(void* const* d_in, const int* in_sizes, int n_in,
                              void* d_out, int out_size) {
    const float* P = (const float*)d_in[0];   // predicts (2,4,64,256,256)
    const float* T = (const float*)d_in[1];   // targets  (2,4,64,256,256)
    const float* M = (const float*)d_in[2];   // masks    (2,1,64,256,256)
    float* out = (float*)d_out;

    dim3 grid(254, NSEG);        // 2032 blocks x 4 warps
    vort_kernel<<<grid, 128>>>(P, T, M);
    final_kernel<<<1, 1>>>(out);
}